// round 17
// baseline (speedup 1.0000x reference)
#include <cuda_runtime.h>
#include <cuda_fp16.h>
#include <math.h>
#include <stdint.h>

// ---------------- problem constants ----------------
#define M_TOK 8192
#define DD    1024
#define FF    4096
#define EE    4
#define N1    16384
#define SMASK 2047

// ---------------- scratch (__device__ globals; no allocs allowed) ----------
__device__ float   g_c [M_TOK * EE];
__device__ int     g_cnt[EE];
__device__ int     g_list[EE * M_TOK];
__device__ int     g_pos[M_TOK * EE];
__device__ __half  g_x [(size_t)M_TOK * DD];
__device__ __half  g_w1[(size_t)EE * DD * FF];     // fp16, native [E][D][F]
__device__ __half  g_w2[(size_t)N1 * DD];          // fp16, native [E*F][D]
__device__ __half  g_H [(size_t)EE * M_TOK * FF];
__device__ float   g_y [(size_t)EE * M_TOK * DD];

// ---------------- helpers ----------------
__device__ __forceinline__ uint32_t smem_u32(const void* p) {
    uint32_t a;
    asm("{ .reg .u64 t; cvta.to.shared.u64 t, %1; cvt.u32.u64 %0, t; }" : "=r"(a) : "l"(p));
    return a;
}
#define CP16(sm, g)   asm volatile("cp.async.cg.shared.global [%0], [%1], 16;" :: "r"(sm), "l"(g) : "memory")
#define CP_COMMIT()   asm volatile("cp.async.commit_group;" ::: "memory")
#define CP_WAIT(n)    asm volatile("cp.async.wait_group %0;" :: "n"(n) : "memory")

#define LDMX4(r, a) asm volatile( \
    "ldmatrix.sync.aligned.m8n8.x4.shared.b16 {%0,%1,%2,%3}, [%4];" \
    : "=r"((r)[0]), "=r"((r)[1]), "=r"((r)[2]), "=r"((r)[3]) : "r"(a))
#define LDMX4T(r, a) asm volatile( \
    "ldmatrix.sync.aligned.m8n8.x4.trans.shared.b16 {%0,%1,%2,%3}, [%4];" \
    : "=r"((r)[0]), "=r"((r)[1]), "=r"((r)[2]), "=r"((r)[3]) : "r"(a))
#define MMA16816(d, a, b) asm volatile( \
    "mma.sync.aligned.m16n8k16.row.col.f32.f16.f16.f32 " \
    "{%0,%1,%2,%3}, {%4,%5,%6,%7}, {%8,%9}, {%0,%1,%2,%3};" \
    : "+f"((d)[0]), "+f"((d)[1]), "+f"((d)[2]), "+f"((d)[3]) \
    : "r"((a)[0]), "r"((a)[1]), "r"((a)[2]), "r"((a)[3]), "r"((b)[0]), "r"((b)[1]))

// A tile: 256 rows x 128B (64 k fp16). swizzle chunk(16B) ^ (row&7).
__device__ __forceinline__ uint32_t a_addr(uint32_t base, int r, int kb) {
    return base + (uint32_t)r * 128u + ((uint32_t)(((kb >> 4) ^ (r & 7)) & 7) << 4);
}
// B tile: 64 k-rows x (BN*2)B. chunk(16B): keep high bits, xor low3 with k.
template <int ROWB>
__device__ __forceinline__ uint32_t b_addr(uint32_t base, int k, int chunk) {
    uint32_t ch = (uint32_t)((chunk & ~7) | ((chunk ^ k) & 7));
    return base + (uint32_t)k * (uint32_t)ROWB + (ch << 4);
}

// ---------------------------------------------------------------------------
// coeff + list build + x fp16 conversion, fused (g_cnt zeroed first)
// ---------------------------------------------------------------------------
__global__ __launch_bounds__(256) void coeff_kernel(
    const float* __restrict__ x, const float* __restrict__ Wu,
    const float* __restrict__ bu, __half* __restrict__ xf)
{
    int t = blockIdx.x * 8 + (threadIdx.x >> 5);
    int lane = threadIdx.x & 31;
    if (t >= M_TOK) return;
    const float4* xr = (const float4*)(x + (size_t)t * DD);
    const float4* wr = (const float4*)Wu;
    __half2* xo = (__half2*)(xf + (size_t)t * DD);
    float sum = 0.f;
#pragma unroll
    for (int i = lane; i < DD / 4; i += 32) {
        float4 a = xr[i], b = wr[i];
        sum += a.x * b.x + a.y * b.y + a.z * b.z + a.w * b.w;
        xo[i * 2]     = __half2(__float2half(a.x), __float2half(a.y));
        xo[i * 2 + 1] = __half2(__float2half(a.z), __float2half(a.w));
    }
#pragma unroll
    for (int o = 16; o; o >>= 1) sum += __shfl_xor_sync(0xffffffffu, sum, o);
    if (lane == 0) {
        float z = sum + bu[0];
        float u = 1.f / (1.f + expf(-z));
        int k = (int)ceilf(u * (float)EE);
        k = k < 1 ? 1 : (k > EE ? EE : k);
        int s = t & SMASK;
#pragma unroll
        for (int e = 0; e < EE; e++) {
            int ie = ((e - s) & 3) + 1;
            float c = (k >= ie) ? (u / (float)ie) : 0.f;
            g_c[t * EE + e] = c;
            if (c != 0.f) {
                int p = atomicAdd(&g_cnt[e], 1);
                g_list[e * M_TOK + p] = t;
                g_pos[t * EE + e] = p;
            }
        }
    }
}

__global__ void init_cnt_kernel() {
    if (threadIdx.x < EE) g_cnt[threadIdx.x] = 0;
}

// ---------------------------------------------------------------------------
// fp32 -> fp16 elementwise, 2x float4 per thread (weights)
// ---------------------------------------------------------------------------
__global__ __launch_bounds__(256) void convert_h_kernel(
    const float* __restrict__ in, __half* __restrict__ o)
{
    size_t i = ((size_t)blockIdx.x * 256 + threadIdx.x) * 8;
    float4 v0 = *(const float4*)(in + i);
    float4 v1 = *(const float4*)(in + i + 4);
    __half2 h0(__float2half(v0.x), __float2half(v0.y));
    __half2 h1(__float2half(v0.z), __float2half(v0.w));
    __half2 h2(__float2half(v1.x), __float2half(v1.y));
    __half2 h3(__float2half(v1.z), __float2half(v1.w));
    uint4 pk;
    pk.x = *(uint32_t*)&h0; pk.y = *(uint32_t*)&h1;
    pk.z = *(uint32_t*)&h2; pk.w = *(uint32_t*)&h3;
    *(uint4*)(o + i) = pk;
}

// ---------------------------------------------------------------------------
// sparse per-expert fp16 GEMM, BK=64, 4-stage cp.async, 8 warps.
// MODE1: 256x128 CTA tile (4Mx2N warps, 64x64). A = x gathered, B = W1[e],
//        relu(acc+b1)*c -> H_e fp16.   grid (M_TOK/256, FF/128, e)
// MODE2: 256x64 CTA tile (4Mx2N warps, 64x32). A = H_e, B = W2[e],
//        C = y_e fp32.                 grid (DD/64, M_TOK/256, e)
//        Smaller grain cuts the last-wave quantization tail.
// ---------------------------------------------------------------------------
template <int MODE>
__global__ __launch_bounds__(256, 1) void gemm_kernel(
    const __half* __restrict__ Af, const __half* __restrict__ Bf,
    const float* __restrict__ bias,
    __half* __restrict__ Ch, float* __restrict__ Yo)
{
    constexpr int KTOT = (MODE == 1) ? DD : FF;
    constexpr int NK   = KTOT / 64;
    constexpr int BN   = (MODE == 1) ? 128 : 64;    // CTA N width
    constexpr int ROWB = BN * 2;                    // B tile row bytes
    constexpr int NCH  = BN / 8;                    // 16B chunks per B row
    constexpr int NI   = BN / 16;                   // n8 groups per warp (8 / 4)
    constexpr int NP   = NI / 2;                    // x4T loads per warp (4 / 2)
    constexpr uint32_t STAGE = 32768u + (uint32_t)(64 * ROWB);
    constexpr int LTOT = 2048 + 64 * NCH;           // cp.async entries/stage

    extern __shared__ char smem[];
    uint32_t sbase = smem_u32(smem);
    int* sList = (int*)(smem + 4 * STAGE);

    const int tid = threadIdx.x;
    const int lane = tid & 31;
    const int wid = tid >> 5;
    const int wm = wid >> 1;          // 0..3 -> M offset wm*64
    const int wn = wid & 1;           // 0..1 -> N offset wn*(BN/2)

    const int e = blockIdx.z;
    const int n_e = g_cnt[e];
    const int mtiles = (n_e + 255) >> 8;
    const int mt = (MODE == 1) ? blockIdx.x : blockIdx.y;
    if (mt >= mtiles) return;
    const int bm = mt * 256;
    const int bn = ((MODE == 1) ? blockIdx.y : blockIdx.x) * BN;

    if (MODE == 1) {
        int idx = bm + tid;
        sList[tid] = (idx < n_e) ? g_list[e * M_TOK + idx] : 0;
        __syncthreads();
    }

    auto load_chunk = [&](int k0, int slot) {
        uint32_t base = sbase + (uint32_t)slot * STAGE;
#pragma unroll
        for (int q = 0; q < LTOT / 256; q++) {
            int lin = tid + q * 256;
            const __half* src;
            uint32_t dst;
            if (lin < 2048) {                     // A: 256 rows x 8 seg16B
                int r  = lin >> 3;
                int cq = lin & 7;
                int ke = k0 + cq * 8;
                if (MODE == 1) src = Af + (size_t)sList[r] * DD + ke;
                else           src = Af + (size_t)e * M_TOK * FF + (size_t)(bm + r) * FF + ke;
                dst = a_addr(base, r, cq * 16);
            } else {                              // B: 64 k-rows x NCH seg16B
                int l2 = lin - 2048;
                int k  = l2 / NCH;
                int cq = l2 % NCH;
                if (MODE == 1)
                    src = Bf + (size_t)e * DD * FF + (size_t)(k0 + k) * FF + bn + cq * 8;
                else
                    src = Bf + (size_t)(e * FF + k0 + k) * DD + bn + cq * 8;
                dst = b_addr<ROWB>(base + 32768u, k, cq);
            }
            CP16(dst, src);
        }
        CP_COMMIT();
    };

    float acc[4][NI][4];
#pragma unroll
    for (int mi = 0; mi < 4; mi++)
#pragma unroll
        for (int ni = 0; ni < NI; ni++)
#pragma unroll
            for (int j = 0; j < 4; j++) acc[mi][ni][j] = 0.f;

    load_chunk(0, 0);
    load_chunk(64, 1);
    load_chunk(128, 2);

    const int a_row = lane & 15;
    const int a_sel = ((lane >> 4) & 1) * 16;     // 16B half within k16
    const int bt_k  = lane & 15;                  // trans: k within k16
    const int bt_n8 = (lane >> 4) & 1;            // n8 group select

    for (int i = 0; i < NK; i++) {
        CP_WAIT(2);
        __syncthreads();
        if (i + 3 < NK) load_chunk((i + 3) * 64, (i + 3) & 3);

        uint32_t base = sbase + (uint32_t)(i & 3) * STAGE;
        uint32_t bB = base + 32768u;

#pragma unroll
        for (int ks = 0; ks < 4; ks++) {
            uint32_t aa[4][4], bb[NP][4];
#pragma unroll
            for (int mi = 0; mi < 4; mi++) {
                int r = wm * 64 + mi * 16 + a_row;
                LDMX4(aa[mi], a_addr(base, r, ks * 32 + a_sel));
            }
#pragma unroll
            for (int np = 0; np < NP; np++) {
                int k = ks * 16 + bt_k;
                int chunk = wn * (NCH / 2) + np * 2 + bt_n8;
                LDMX4T(bb[np], b_addr<ROWB>(bB, k, chunk));
            }
#pragma unroll
            for (int mi = 0; mi < 4; mi++)
#pragma unroll
                for (int np = 0; np < NP; np++) {
                    MMA16816(acc[mi][np * 2],     aa[mi], (&bb[np][0]));
                    MMA16816(acc[mi][np * 2 + 1], aa[mi], (&bb[np][2]));
                }
        }
    }
    CP_WAIT(0);
    __syncthreads();

    // acc(mi,ni,j): row = wm*64+mi*16+(lane>>2)+(j>>1)*8
    //               col = wn*(BN/2)+ni*8+(lane&3)*2+(j&1)
    if (MODE == 1) {
        float bv[NI][2];
#pragma unroll
        for (int ni = 0; ni < NI; ni++) {
            int c0 = wn * 64 + ni * 8 + (lane & 3) * 2;
            bv[ni][0] = bias[(size_t)e * FF + bn + c0];
            bv[ni][1] = bias[(size_t)e * FF + bn + c0 + 1];
        }
#pragma unroll
        for (int mi = 0; mi < 4; mi++)
#pragma unroll
            for (int h = 0; h < 2; h++) {
                int row = wm * 64 + mi * 16 + (lane >> 2) + h * 8;
                float cv = (bm + row < n_e) ? g_c[sList[row] * EE + e] : 0.f;
#pragma unroll
                for (int ni = 0; ni < NI; ni++) {
                    int c0 = wn * 64 + ni * 8 + (lane & 3) * 2;
                    float v0 = fmaxf(acc[mi][ni][h * 2 + 0] + bv[ni][0], 0.f) * cv;
                    float v1 = fmaxf(acc[mi][ni][h * 2 + 1] + bv[ni][1], 0.f) * cv;
                    *(__half2*)(smem + row * 256 + c0 * 2) =
                        __half2(__float2half(v0), __float2half(v1));
                }
            }
        __syncthreads();
#pragma unroll
        for (int q = 0; q < 16; q++) {
            int lin = tid + q * 256;              // 0..4095
            int r   = lin >> 4;
            int cw  = lin & 15;
            uint4 v = *(uint4*)(smem + r * 256 + cw * 16);
            *(uint4*)(Ch + (size_t)e * M_TOK * FF + (size_t)(bm + r) * FF + bn + cw * 8) = v;
        }
    } else {
        // fp32 256x64 epilogue in two 32KB passes (rows 0-127, 128-255)
#pragma unroll
        for (int pass = 0; pass < 2; pass++) {
            if ((wm >> 1) == pass) {
#pragma unroll
                for (int mi = 0; mi < 4; mi++)
#pragma unroll
                    for (int h = 0; h < 2; h++) {
                        int row = (wm & 1) * 64 + mi * 16 + (lane >> 2) + h * 8;
#pragma unroll
                        for (int ni = 0; ni < NI; ni++) {
                            int c0 = wn * 32 + ni * 8 + (lane & 3) * 2;
                            *(float*)(smem + row * 256 + c0 * 4)       = acc[mi][ni][h * 2 + 0];
                            *(float*)(smem + row * 256 + (c0 + 1) * 4) = acc[mi][ni][h * 2 + 1];
                        }
                    }
            }
            __syncthreads();
#pragma unroll
            for (int q = 0; q < 8; q++) {
                int lin = tid + q * 256;          // 0..2047
                int r   = lin >> 4;               // 0..127
                int cw  = lin & 15;               // 16 uint4 = 64 floats/row
                uint4 v = *(uint4*)(smem + r * 256 + cw * 16);
                *(uint4*)(Yo + (size_t)e * M_TOK * DD +
                          (size_t)(bm + pass * 128 + r) * DD + bn + cw * 4) = v;
            }
            if (pass == 0) __syncthreads();
        }
    }
}

// ---------------------------------------------------------------------------
// final gather: out[t] = sum over active e of (y_e[pos] + c_e*b2_e)
// ---------------------------------------------------------------------------
__global__ __launch_bounds__(256) void gather_out_kernel(
    const float* __restrict__ y, const float* __restrict__ b2,
    float* __restrict__ out)
{
    int t = blockIdx.x;
    int d = threadIdx.x * 4;
    float acc0 = 0.f, acc1 = 0.f, acc2 = 0.f, acc3 = 0.f;
#pragma unroll
    for (int e = 0; e < EE; e++) {
        float c = g_c[t * EE + e];
        if (c != 0.f) {
            int pos = g_pos[t * EE + e];
            float4 vy = *(const float4*)(y + (size_t)e * M_TOK * DD + (size_t)pos * DD + d);
            float4 vb = *(const float4*)(b2 + e * DD + d);
            acc0 += vy.x + c * vb.x;
            acc1 += vy.y + c * vb.y;
            acc2 += vy.z + c * vb.z;
            acc3 += vy.w + c * vb.w;
        }
    }
    float4 o = {acc0, acc1, acc2, acc3};
    *(float4*)(out + (size_t)t * DD + d) = o;
}

// ---------------------------------------------------------------------------
// launch. Inputs: x, W1, b1, W2, b2, Wu, bu
// ---------------------------------------------------------------------------
extern "C" void kernel_launch(void* const* d_in, const int* in_sizes, int n_in,
                              void* d_out, int out_size)
{
    const float* x  = (const float*)d_in[0];
    const float* W1 = (const float*)d_in[1];
    const float* b1 = (const float*)d_in[2];
    const float* W2 = (const float*)d_in[3];
    const float* b2 = (const float*)d_in[4];
    const float* Wu = (const float*)d_in[5];
    const float* bu = (const float*)d_in[6];
    float* out = (float*)d_out;
    (void)in_sizes; (void)n_in; (void)out_size;

    __half *xf, *w1, *w2, *H;
    float* y;
    cudaGetSymbolAddress((void**)&xf, g_x);
    cudaGetSymbolAddress((void**)&w1, g_w1);
    cudaGetSymbolAddress((void**)&w2, g_w2);
    cudaGetSymbolAddress((void**)&H,  g_H);
    cudaGetSymbolAddress((void**)&y,  g_y);

    const int SMEM_G1 = 4 * 49152 + 1024;   // 197632
    const int SMEM_G2 = 4 * 40960 + 1024;   // 164864
    cudaFuncSetAttribute(gemm_kernel<1>,
                         cudaFuncAttributeMaxDynamicSharedMemorySize, SMEM_G1);
    cudaFuncSetAttribute(gemm_kernel<2>,
                         cudaFuncAttributeMaxDynamicSharedMemorySize, SMEM_G2);

    init_cnt_kernel<<<1, 32>>>();
    // coeff + list build + x fp16 conversion (one pass over x)
    coeff_kernel<<<M_TOK / 8, 256>>>(x, Wu, bu, xf);

    // weight converts (layout preserved), 8 floats/thread
    convert_h_kernel<<<(EE * DD * FF) / 2048, 256>>>(W1, w1);
    convert_h_kernel<<<(N1 * DD) / 2048, 256>>>(W2, w2);

    {   // GEMM1 sparse: per-expert [n_e,1024] x [1024,4096] -> H_e fp16
        dim3 grid(M_TOK / 256, FF / 128, EE);   // Mtile fast (B-panel reuse)
        gemm_kernel<1><<<grid, 256, SMEM_G1>>>(xf, w1, b1, H, nullptr);
    }
    {   // GEMM2 sparse: per-expert [n_e,4096] x [4096,1024] -> y_e fp32
        // 256x64 tiles: finer grain to cut last-wave quantization tail
        dim3 grid(DD / 64, M_TOK / 256, EE);    // Ntile fast (A-panel reuse)
        gemm_kernel<2><<<grid, 256, SMEM_G2>>>(H, w2, nullptr, nullptr, y);
    }

    gather_out_kernel<<<M_TOK, 256>>>(y, b2, out);
}